// round 3
// baseline (speedup 1.0000x reference)
#include <cuda_runtime.h>
#include <stdint.h>

// Problem constants
#define BATCH   32
#define NATOM   256
#define NN      100
#define NFEAT   42
#define H       50
#define NATOMS  (BATCH * NATOM)          // 8192
#define DF_PER_ATOM (NN * NFEAT * 3)     // 12600

// Scratch: per-atom input gradient dE/dx  (32*256*42 floats = 1.37 MB)
__device__ float g_dE[NATOMS * NFEAT];

// ---------------------------------------------------------------------------
// Kernel A: per-atom MLP forward + input gradient. One warp per atom.
// Block = 256 threads = 8 warps = 8 consecutive atoms (same type: 8 | 128).
// ---------------------------------------------------------------------------
__global__ __launch_bounds__(256) void fc_kernel(
    const float* __restrict__ image,
    const float* __restrict__ W0t0, const float* __restrict__ b0t0,
    const float* __restrict__ W1t0, const float* __restrict__ b1t0,
    const float* __restrict__ W2t0, const float* __restrict__ b2t0,
    const float* __restrict__ W0t1, const float* __restrict__ b0t1,
    const float* __restrict__ W1t1, const float* __restrict__ b1t1,
    const float* __restrict__ W2t1, const float* __restrict__ b2t1,
    float* __restrict__ Ei_out)
{
    __shared__ float W0s[NFEAT * H];   // 2100
    __shared__ float W1s[H * H];       // 2500
    __shared__ float W2s[H], b0s[H], b1s[H];
    __shared__ float b2s;
    __shared__ float xs[8][NFEAT];
    __shared__ float h0s[8][H];
    __shared__ float g1s[8][H];
    __shared__ float g0s[8][H];

    const int tid = threadIdx.x;
    const int w   = tid >> 5;
    const int l   = tid & 31;
    const int atom = blockIdx.x * 8 + w;
    const int n = atom & (NATOM - 1);
    const int type = (n >= 128) ? 1 : 0;

    const float* W0 = type ? W0t1 : W0t0;
    const float* B0 = type ? b0t1 : b0t0;
    const float* W1 = type ? W1t1 : W1t0;
    const float* B1 = type ? b1t1 : b1t0;
    const float* W2 = type ? W2t1 : W2t0;
    const float* B2 = type ? b2t1 : b2t0;

    for (int i = tid; i < NFEAT * H; i += 256) W0s[i] = W0[i];
    for (int i = tid; i < H * H;     i += 256) W1s[i] = W1[i];
    if (tid < H) { W2s[tid] = W2[tid]; b0s[tid] = B0[tid]; b1s[tid] = B1[tid]; }
    if (tid == 0) b2s = B2[0];
    __syncthreads();

    // load x (42 floats) for this warp's atom
    const float* xg = image + (size_t)atom * NFEAT;
    for (int f = l; f < NFEAT; f += 32) xs[w][f] = xg[f];
    __syncwarp();

    const bool hi = (l < H - 32);   // l < 18: handles output index l+32

    // ---- layer 0: h0 = tanh(x @ W0 + b0) ----
    float h0a = b0s[l];
    float h0b = hi ? b0s[l + 32] : 0.f;
    #pragma unroll
    for (int f = 0; f < NFEAT; ++f) {
        float xv = xs[w][f];
        h0a = fmaf(W0s[f * H + l], xv, h0a);
        if (hi) h0b = fmaf(W0s[f * H + l + 32], xv, h0b);
    }
    h0a = tanhf(h0a);
    if (hi) h0b = tanhf(h0b);
    h0s[w][l] = h0a;
    if (hi) h0s[w][l + 32] = h0b;
    __syncwarp();

    // ---- layer 1: h1 = tanh(h0 @ W1 + b1) ----
    float h1a = b1s[l];
    float h1b = hi ? b1s[l + 32] : 0.f;
    #pragma unroll
    for (int i = 0; i < H; ++i) {
        float hv = h0s[w][i];
        h1a = fmaf(W1s[i * H + l], hv, h1a);
        if (hi) h1b = fmaf(W1s[i * H + l + 32], hv, h1b);
    }
    h1a = tanhf(h1a);
    if (hi) h1b = tanhf(h1b);

    // ---- Ei = h1 @ W2 + b2 ----
    float p = h1a * W2s[l] + (hi ? h1b * W2s[l + 32] : 0.f);
    #pragma unroll
    for (int off = 16; off > 0; off >>= 1)
        p += __shfl_down_sync(0xFFFFFFFFu, p, off);
    if (l == 0) Ei_out[atom] = p + b2s;

    // ---- backward: g1 = W2 * (1 - h1^2) ----
    g1s[w][l] = W2s[l] * (1.f - h1a * h1a);
    if (hi) g1s[w][l + 32] = W2s[l + 32] * (1.f - h1b * h1b);
    __syncwarp();

    // ---- g0[i] = (sum_j W1[i,j] * g1[j]) * (1 - h0[i]^2) ----
    float ga = 0.f, gb = 0.f;
    #pragma unroll
    for (int j = 0; j < H; ++j) {
        float gv = g1s[w][j];
        ga = fmaf(W1s[l * H + j], gv, ga);
        if (hi) gb = fmaf(W1s[(l + 32) * H + j], gv, gb);
    }
    ga *= (1.f - h0a * h0a);
    if (hi) gb *= (1.f - h0b * h0b);
    g0s[w][l] = ga;
    if (hi) g0s[w][l + 32] = gb;
    __syncwarp();

    // ---- dx[f] = sum_i W0[f,i] * g0[i] ----  (f = l and l+32 for l<10)
    float da = 0.f, db = 0.f;
    #pragma unroll
    for (int i = 0; i < H; ++i) {
        float gv = g0s[w][i];
        da = fmaf(W0s[l * H + i], gv, da);
        if (l < NFEAT - 32) db = fmaf(W0s[(l + 32) * H + i], gv, db);
    }
    float* dE = g_dE + (size_t)atom * NFEAT;
    dE[l] = da;
    if (l < NFEAT - 32) dE[l + 32] = db;
}

// ---------------------------------------------------------------------------
// Kernel B: Etot[b] = sum_n Ei[b, n]. One block per batch.
// ---------------------------------------------------------------------------
__global__ __launch_bounds__(256) void etot_kernel(
    const float* __restrict__ Ei, float* __restrict__ Etot)
{
    __shared__ float s[256];
    int b = blockIdx.x, tid = threadIdx.x;
    float v = Ei[b * NATOM + tid];
    s[tid] = v;
    __syncthreads();
    for (int off = 128; off > 0; off >>= 1) {
        if (tid < off) s[tid] += s[tid + off];
        __syncthreads();
    }
    if (tid == 0) Etot[b] = s[0];
}

// ---------------------------------------------------------------------------
// Kernel C: Force[b,n,d] = sum_{k,f} dE_pad[b, nbr[b,n,k], f] * dfeat[b,n,k,f,d]
// One block per (b,n). 128 threads; thread tid<126 owns fixed (f,d)=(tid/3,tid%3).
// NOTE: neighbor is int32 on device (JAX x64 disabled downcasts jnp.int64).
// ---------------------------------------------------------------------------
__global__ __launch_bounds__(128) void force_kernel(
    const float* __restrict__ dfeat,
    const int* __restrict__ neighbor,
    float* __restrict__ force)
{
    __shared__ int   nbr[NN];
    __shared__ float dEs[NN * NFEAT];   // 4200 floats, zero row handled inline
    __shared__ float partial[128];

    const int tid  = threadIdx.x;
    const int atom = blockIdx.x;
    const int b    = atom >> 8;

    const int* nb = neighbor + (size_t)atom * NN;
    if (tid < NN) nbr[tid] = nb[tid];
    __syncthreads();

    // gather neighbor dE rows (L2-resident g_dE); neighbor==0 -> zero row
    for (int idx = tid; idx < NN * NFEAT; idx += 128) {
        int k = idx / NFEAT;
        int f = idx - k * NFEAT;
        int v = nbr[k];
        dEs[idx] = v ? g_dE[((size_t)(b * NATOM + v - 1)) * NFEAT + f] : 0.f;
    }
    __syncthreads();

    // stream dfeat (contiguous 12600 floats per atom), streaming loads
    const float* df = dfeat + (size_t)atom * DF_PER_ATOM;
    float acc = 0.f;
    if (tid < NFEAT * 3) {
        const int f = tid / 3;
        #pragma unroll 5
        for (int k = 0; k < NN; ++k)
            acc = fmaf(dEs[k * NFEAT + f], __ldcs(df + k * (NFEAT * 3) + tid), acc);
    }
    partial[tid] = acc;
    __syncthreads();

    if (tid < 3) {
        float s = 0.f;
        #pragma unroll
        for (int i = tid; i < NFEAT * 3; i += 3) s += partial[i];
        force[(size_t)atom * 3 + tid] = s;
    }
}

// ---------------------------------------------------------------------------
// Launch. Output layout (fp32): [Etot(32) | Ei(8192) | Force(24576)] = 32800
// ---------------------------------------------------------------------------
extern "C" void kernel_launch(void* const* d_in, const int* in_sizes, int n_in,
                              void* d_out, int out_size)
{
    const float* image    = (const float*)d_in[0];
    const float* dfeat    = (const float*)d_in[1];
    const int*   neighbor = (const int*)d_in[2];
    const float *W0t0 = (const float*)d_in[3],  *b0t0 = (const float*)d_in[4];
    const float *W1t0 = (const float*)d_in[5],  *b1t0 = (const float*)d_in[6];
    const float *W2t0 = (const float*)d_in[7],  *b2t0 = (const float*)d_in[8];
    const float *W0t1 = (const float*)d_in[9],  *b0t1 = (const float*)d_in[10];
    const float *W1t1 = (const float*)d_in[11], *b1t1 = (const float*)d_in[12];
    const float *W2t1 = (const float*)d_in[13], *b2t1 = (const float*)d_in[14];

    float* out    = (float*)d_out;
    float* etot   = out;
    float* ei     = out + BATCH;
    float* forceo = out + BATCH + NATOMS;

    fc_kernel<<<NATOMS / 8, 256>>>(image,
        W0t0, b0t0, W1t0, b1t0, W2t0, b2t0,
        W0t1, b0t1, W1t1, b1t1, W2t1, b2t1,
        ei);
    etot_kernel<<<BATCH, 256>>>(ei, etot);
    force_kernel<<<NATOMS, 128>>>(dfeat, neighbor, forceo);
}

// round 8
// speedup vs baseline: 1.1252x; 1.1252x over previous
#include <cuda_runtime.h>
#include <stdint.h>

// Problem constants
#define BATCH   32
#define NATOM   256
#define NN      100
#define NFEAT   42
#define H       50
#define NATOMS  (BATCH * NATOM)          // 8192
#define DF_PER_ATOM (NN * NFEAT * 3)     // 12600
#define DE_PAD  48                       // padded dE row (12 float4)

// Scratch: per-atom input gradient dE/dx, rows padded to 48 floats (1.57 MB)
__device__ float g_dE[NATOMS * DE_PAD];

// Fast accurate tanh: 1 - 2/(e^{2x}+1). ~5 inst, ~1e-7 rel err. Saturates correctly.
__device__ __forceinline__ float tanh_fast(float x) {
    float e = __expf(2.0f * x);
    return 1.0f - __fdividef(2.0f, e + 1.0f);
}

#define W0P 51   // padded row stride for W0s (42 x 51)
#define W1P 51   // padded row stride for W1s (50 x 51)

// ---------------------------------------------------------------------------
// Kernel A: per-atom MLP forward + input gradient. One warp per atom.
// Block = 256 threads = 8 warps = 8 consecutive atoms (same type: 8 | 128).
// ---------------------------------------------------------------------------
__global__ __launch_bounds__(256) void fc_kernel(
    const float* __restrict__ image,
    const float* __restrict__ W0t0, const float* __restrict__ b0t0,
    const float* __restrict__ W1t0, const float* __restrict__ b1t0,
    const float* __restrict__ W2t0, const float* __restrict__ b2t0,
    const float* __restrict__ W0t1, const float* __restrict__ b0t1,
    const float* __restrict__ W1t1, const float* __restrict__ b1t1,
    const float* __restrict__ W2t1, const float* __restrict__ b2t1,
    float* __restrict__ Ei_out)
{
    __shared__ float W0s[NFEAT * W0P];   // padded rows: [f][i]
    __shared__ float W1s[H * W1P];       // padded rows: [i][j]
    __shared__ float W2s[H], b0s[H], b1s[H];
    __shared__ float b2s;
    __shared__ float xs[8][NFEAT];
    __shared__ float h0s[8][H];
    __shared__ float g1s[8][H];
    __shared__ float g0s[8][H];

    const int tid = threadIdx.x;
    const int w   = tid >> 5;
    const int l   = tid & 31;
    const int atom = blockIdx.x * 8 + w;
    const int n = atom & (NATOM - 1);
    const int type = (n >= 128) ? 1 : 0;

    const float* W0 = type ? W0t1 : W0t0;
    const float* B0 = type ? b0t1 : b0t0;
    const float* W1 = type ? W1t1 : W1t0;
    const float* B1 = type ? b1t1 : b1t0;
    const float* W2 = type ? W2t1 : W2t0;
    const float* B2 = type ? b2t1 : b2t0;

    for (int i = tid; i < NFEAT * H; i += 256) W0s[(i / H) * W0P + (i % H)] = W0[i];
    for (int i = tid; i < H * H;     i += 256) W1s[(i / H) * W1P + (i % H)] = W1[i];
    if (tid < H) { W2s[tid] = W2[tid]; b0s[tid] = B0[tid]; b1s[tid] = B1[tid]; }
    if (tid == 0) b2s = B2[0];
    __syncthreads();

    // load x (42 floats) for this warp's atom
    const float* xg = image + (size_t)atom * NFEAT;
    for (int f = l; f < NFEAT; f += 32) xs[w][f] = xg[f];
    __syncwarp();

    const bool hi = (l < H - 32);   // l < 18: handles output index l+32

    // ---- layer 0: h0 = tanh(x @ W0 + b0) ----
    float h0a = b0s[l];
    float h0b = hi ? b0s[l + 32] : 0.f;
    #pragma unroll
    for (int f = 0; f < NFEAT; ++f) {
        float xv = xs[w][f];
        h0a = fmaf(W0s[f * W0P + l], xv, h0a);
        if (hi) h0b = fmaf(W0s[f * W0P + l + 32], xv, h0b);
    }
    h0a = tanh_fast(h0a);
    if (hi) h0b = tanh_fast(h0b);
    h0s[w][l] = h0a;
    if (hi) h0s[w][l + 32] = h0b;
    __syncwarp();

    // ---- layer 1: h1 = tanh(h0 @ W1 + b1) ----
    float h1a = b1s[l];
    float h1b = hi ? b1s[l + 32] : 0.f;
    #pragma unroll
    for (int i = 0; i < H; ++i) {
        float hv = h0s[w][i];
        h1a = fmaf(W1s[i * W1P + l], hv, h1a);
        if (hi) h1b = fmaf(W1s[i * W1P + l + 32], hv, h1b);
    }
    h1a = tanh_fast(h1a);
    if (hi) h1b = tanh_fast(h1b);

    // ---- Ei = h1 @ W2 + b2 ----
    float p = h1a * W2s[l] + (hi ? h1b * W2s[l + 32] : 0.f);
    #pragma unroll
    for (int off = 16; off > 0; off >>= 1)
        p += __shfl_down_sync(0xFFFFFFFFu, p, off);
    if (l == 0) Ei_out[atom] = p + b2s;

    // ---- backward: g1 = W2 * (1 - h1^2) ----
    g1s[w][l] = W2s[l] * (1.f - h1a * h1a);
    if (hi) g1s[w][l + 32] = W2s[l + 32] * (1.f - h1b * h1b);
    __syncwarp();

    // ---- g0[i] = (sum_j W1[i,j] * g1[j]) * (1 - h0[i]^2) ----
    float ga = 0.f, gb = 0.f;
    #pragma unroll
    for (int j = 0; j < H; ++j) {
        float gv = g1s[w][j];
        ga = fmaf(W1s[l * W1P + j], gv, ga);
        if (hi) gb = fmaf(W1s[(l + 32) * W1P + j], gv, gb);
    }
    ga *= (1.f - h0a * h0a);
    if (hi) gb *= (1.f - h0b * h0b);
    g0s[w][l] = ga;
    if (hi) g0s[w][l + 32] = gb;
    __syncwarp();

    // ---- dx[f] = sum_i W0[f,i] * g0[i] ----  (f = l and l+32 for l<10)
    float da = 0.f, db = 0.f;
    #pragma unroll
    for (int i = 0; i < H; ++i) {
        float gv = g0s[w][i];
        da = fmaf(W0s[l * W0P + i], gv, da);
        if (l < NFEAT - 32) db = fmaf(W0s[(l + 32) * W0P + i], gv, db);
    }
    float* dE = g_dE + (size_t)atom * DE_PAD;
    dE[l] = da;
    if (l < NFEAT - 32) dE[l + 32] = db;
}

// ---------------------------------------------------------------------------
// Kernel B: Etot[b] = sum_n Ei[b, n]. One block per batch.
// ---------------------------------------------------------------------------
__global__ __launch_bounds__(256) void etot_kernel(
    const float* __restrict__ Ei, float* __restrict__ Etot)
{
    __shared__ float s[256];
    int b = blockIdx.x, tid = threadIdx.x;
    float v = Ei[b * NATOM + tid];
    s[tid] = v;
    __syncthreads();
    for (int off = 128; off > 0; off >>= 1) {
        if (tid < off) s[tid] += s[tid + off];
        __syncthreads();
    }
    if (tid == 0) Etot[b] = s[0];
}

// ---------------------------------------------------------------------------
// Kernel C: Force[b,n,d] = sum_{k,f} dE_pad[b, nbr[b,n,k], f] * dfeat[b,n,k,f,d]
// One block per (b,n). 128 threads.
//   Gather: 1200 float4 loads from padded g_dE rows (batched, latency-hidden).
//   Stream: float2 loads, two k-rows in flight (lanes 0-62: k, 64-126: k+1).
// ---------------------------------------------------------------------------
__global__ __launch_bounds__(128) void force_kernel(
    const float* __restrict__ dfeat,
    const int* __restrict__ neighbor,
    float* __restrict__ force)
{
    __shared__ int    nbr[NN];
    __shared__ float  dEs[NN * DE_PAD];   // 100 x 48 floats = 19.2 KB
    __shared__ float  partA[126];
    __shared__ float  partB[126];

    const int tid  = threadIdx.x;
    const int atom = blockIdx.x;
    const int b    = atom >> 8;

    const int* nb = neighbor + (size_t)atom * NN;
    if (tid < NN) nbr[tid] = nb[tid];
    __syncthreads();

    // gather neighbor dE rows as float4 (12 per row); neighbor==0 -> zero row
    {
        const float4* gdE4 = (const float4*)g_dE;
        float4* dEs4 = (float4*)dEs;
        const float4 z4 = make_float4(0.f, 0.f, 0.f, 0.f);
        #pragma unroll
        for (int it = 0; it < 10; ++it) {           // 10*128 = 1280 >= 1200
            int idx = tid + it * 128;
            if (idx < NN * (DE_PAD / 4)) {
                int k = idx / (DE_PAD / 4);
                int q = idx - k * (DE_PAD / 4);
                int v = nbr[k];
                dEs4[idx] = v ? gdE4[(size_t)(b * NATOM + v - 1) * (DE_PAD / 4) + q] : z4;
            }
        }
    }
    __syncthreads();

    // stream dfeat: 126 floats per k-row = 63 float2. Lanes split across 2 k's.
    const int half = tid >> 6;           // 0 or 1
    const int tt   = tid & 63;           // 0..63
    const bool act = (tt < 63);
    const int r0 = 2 * tt;               // element index in [0,126)
    const int r1 = 2 * tt + 1;
    const int f0 = r0 / 3;
    const int f1 = r1 / 3;

    const float2* df2 = (const float2*)(dfeat + (size_t)atom * DF_PER_ATOM);
    float acc0 = 0.f, acc1 = 0.f;
    if (act) {
        #pragma unroll 5
        for (int kb = 0; kb < NN; kb += 2) {
            int k = kb + half;
            float2 v = __ldcs(df2 + (size_t)k * 63 + tt);
            acc0 = fmaf(dEs[k * DE_PAD + f0], v.x, acc0);
            acc1 = fmaf(dEs[k * DE_PAD + f1], v.y, acc1);
        }
        if (half == 0) { partA[r0] = acc0; partA[r1] = acc1; }
        else           { partB[r0] = acc0; partB[r1] = acc1; }
    }
    __syncthreads();

    if (tid < 3) {
        float s = 0.f;
        #pragma unroll
        for (int r = tid; r < NFEAT * 3; r += 3) s += partA[r] + partB[r];
        force[(size_t)atom * 3 + tid] = s;
    }
}

// ---------------------------------------------------------------------------
// Launch. Output layout (fp32): [Etot(32) | Ei(8192) | Force(24576)] = 32800
// ---------------------------------------------------------------------------
extern "C" void kernel_launch(void* const* d_in, const int* in_sizes, int n_in,
                              void* d_out, int out_size)
{
    const float* image    = (const float*)d_in[0];
    const float* dfeat    = (const float*)d_in[1];
    const int*   neighbor = (const int*)d_in[2];
    const float *W0t0 = (const float*)d_in[3],  *b0t0 = (const float*)d_in[4];
    const float *W1t0 = (const float*)d_in[5],  *b1t0 = (const float*)d_in[6];
    const float *W2t0 = (const float*)d_in[7],  *b2t0 = (const float*)d_in[8];
    const float *W0t1 = (const float*)d_in[9],  *b0t1 = (const float*)d_in[10];
    const float *W1t1 = (const float*)d_in[11], *b1t1 = (const float*)d_in[12];
    const float *W2t1 = (const float*)d_in[13], *b2t1 = (const float*)d_in[14];

    float* out    = (float*)d_out;
    float* etot   = out;
    float* ei     = out + BATCH;
    float* forceo = out + BATCH + NATOMS;

    fc_kernel<<<NATOMS / 8, 256>>>(image,
        W0t0, b0t0, W1t0, b1t0, W2t0, b2t0,
        W0t1, b0t1, W1t1, b1t1, W2t1, b2t1,
        ei);
    etot_kernel<<<BATCH, 256>>>(ei, etot);
    force_kernel<<<NATOMS, 128>>>(dfeat, neighbor, forceo);
}